// round 15
// baseline (speedup 1.0000x reference)
#include <cuda_runtime.h>
#include <cuda_fp16.h>
#include <cstdint>

#define NN 50000
#define EE 800000
#define SCAN_BLK ((NN + 1023) / 1024)   // 49

// ---------------- device scratch (no allocations allowed) ----------------
__device__ __align__(16) int    g_outdeg[NN];
__device__ __align__(16) int    g_indeg[NN];
__device__ __align__(16) int    g_cursor[NN];
__device__ __align__(16) int    g_rowptr[NN + 1];
__device__ __align__(16) int    g_esrc[EE];
__device__ __align__(16) int    g_bsum[SCAN_BLK];
__device__ __align__(16) float  g_norm_src[NN];
__device__ __align__(16) float  g_norm_dst[NN];
__device__ __align__(16) __half g_x16[(size_t)NN * 64];   // x * norm_src, fp16
__device__ __align__(16) __half g_agg1[(size_t)NN * 64];
__device__ __align__(16) __half g_h2[(size_t)NN * 64];

__device__ __forceinline__ uint32_t f2tf32(float v) {
    uint32_t u;
    asm("cvt.rna.tf32.f32 %0, %1;" : "=r"(u) : "f"(v));
    return u;
}

#define MMA_TF32(c0, c1, c2, c3, a0, a1, a2, a3, b0, b1) \
    asm volatile("mma.sync.aligned.m16n8k8.row.col.f32.tf32.tf32.f32 " \
        "{%0,%1,%2,%3}, {%4,%5,%6,%7}, {%8,%9}, {%0,%1,%2,%3};" \
        : "+f"(c0), "+f"(c1), "+f"(c2), "+f"(c3) \
        : "r"(a0), "r"(a1), "r"(a2), "r"(a3), "r"(b0), "r"(b1))

__device__ __forceinline__ void h8_to_f8(uint4 raw, float* f) {
    float2 p;
    p = __half22float2(*reinterpret_cast<__half2*>(&raw.x)); f[0] = p.x; f[1] = p.y;
    p = __half22float2(*reinterpret_cast<__half2*>(&raw.y)); f[2] = p.x; f[3] = p.y;
    p = __half22float2(*reinterpret_cast<__half2*>(&raw.z)); f[4] = p.x; f[5] = p.y;
    p = __half22float2(*reinterpret_cast<__half2*>(&raw.w)); f[6] = p.x; f[7] = p.y;
}

// ---------------- preprocessing ----------------
__global__ void k_zero() {
    int i = blockIdx.x * blockDim.x + threadIdx.x;
    if (i < NN) { g_outdeg[i] = 0; g_indeg[i] = 0; }
}

__global__ void k_degree(const int* __restrict__ src, const int* __restrict__ dst) {
    int e = blockIdx.x * blockDim.x + threadIdx.x;
    if (e < EE) {
        atomicAdd(&g_outdeg[src[e]], 1);
        atomicAdd(&g_indeg[dst[e]], 1);
    }
}

// per-block inclusive scan of indeg; norms fused (R13-proven)
__global__ void k_scan_blk() {
    __shared__ int sh[1024];
    int t = threadIdx.x;
    int i = blockIdx.x * 1024 + t;
    int deg = (i < NN) ? g_indeg[i] : 0;
    if (i < NN) {
        g_norm_dst[i] = rsqrtf((float)max(deg, 1));
        g_norm_src[i] = rsqrtf((float)max(g_outdeg[i], 1));
    }
    sh[t] = deg;
    __syncthreads();
    #pragma unroll
    for (int off = 1; off < 1024; off <<= 1) {
        int x = (t >= off) ? sh[t - off] : 0;
        __syncthreads();
        sh[t] += x;
        __syncthreads();
    }
    if (i < NN) g_rowptr[i + 1] = sh[t];
    if (t == 1023) g_bsum[blockIdx.x] = sh[1023];
}

// add block offsets + cursor init + FUSED x->fp16 conversion scaled by norm_src
__global__ void k_scan_add(const float* __restrict__ x) {
    __shared__ int off;
    int t = threadIdx.x;
    int i = blockIdx.x * 1024 + t;
    if (t < 32) {
        int s = 0;
        for (int b = t; b < blockIdx.x; b += 32) s += g_bsum[b];
        #pragma unroll
        for (int o = 16; o > 0; o >>= 1) s += __shfl_down_sync(0xFFFFFFFFu, s, o);
        if (t == 0) off = s;
    }
    __syncthreads();
    if (i < NN) {
        int v = g_rowptr[i + 1] + off;
        g_rowptr[i + 1] = v;
        if (i + 1 < NN) g_cursor[i + 1] = v;
        if (i == 0) { g_rowptr[0] = 0; g_cursor[0] = 0; }
    }
    // convert this block's 1024 rows: x16[row] = x[row] * norm_src[row]
    // 1024 rows x 8 uint4 = 8192 items, block-cooperative, coalesced
    #pragma unroll
    for (int k = 0; k < 8; k++) {
        int idx = (blockIdx.x * 8192) + t + k * 1024;
        int row = idx >> 3;
        if (row < NN) {
            int c8 = idx & 7;
            float ns = g_norm_src[row];
            const float4* xp = reinterpret_cast<const float4*>(x) + (size_t)row * 16 + c8 * 2;
            float4 a = xp[0], b = xp[1];
            uint4 o;
            *reinterpret_cast<__half2*>(&o.x) = __floats2half2_rn(a.x * ns, a.y * ns);
            *reinterpret_cast<__half2*>(&o.y) = __floats2half2_rn(a.z * ns, a.w * ns);
            *reinterpret_cast<__half2*>(&o.z) = __floats2half2_rn(b.x * ns, b.y * ns);
            *reinterpret_cast<__half2*>(&o.w) = __floats2half2_rn(b.z * ns, b.w * ns);
            reinterpret_cast<uint4*>(g_x16)[(size_t)row * 8 + c8] = o;
        }
    }
}

__global__ void k_scatter(const int* __restrict__ src, const int* __restrict__ dst) {
    int e = blockIdx.x * blockDim.x + threadIdx.x;
    if (e < EE) {
        int pos = atomicAdd(&g_cursor[dst[e]], 1);
        g_esrc[pos] = src[e];
    }
}

// ---------------- aggregation: plain sum (norm_src pre-folded into x16) ----------------
// LAYER1: feat = g_x16 -> g_agg1 (fp16)
// !LAYER1: feat = g_h2 -> out_arg (fp32, acc*norm_dst + bias)
template <bool LAYER1>
__global__ void __launch_bounds__(256) k_agg(const float* __restrict__ bias,
                                             float* __restrict__ out_arg) {
    const uint4* __restrict__ feat = LAYER1
        ? reinterpret_cast<const uint4*>(g_x16)
        : reinterpret_cast<const uint4*>(g_h2);
    int n = blockIdx.x * 8 + (threadIdx.x >> 5);   // grid*8 == NN
    int lane = threadIdx.x & 31;
    int slot = lane >> 3;
    int fl   = lane & 7;

    int s = g_rowptr[n], e = g_rowptr[n + 1];
    float acc[8] = {0.f, 0.f, 0.f, 0.f, 0.f, 0.f, 0.f, 0.f};
    #pragma unroll 2
    for (int j = s + slot; j < e; j += 4) {
        int u = g_esrc[j];
        uint4 raw = feat[(size_t)u * 8 + fl];
        float f[8];
        h8_to_f8(raw, f);
        #pragma unroll
        for (int k = 0; k < 8; k++) acc[k] += f[k];
    }
    #pragma unroll
    for (int o = 16; o >= 8; o >>= 1)
        #pragma unroll
        for (int k = 0; k < 8; k++)
            acc[k] += __shfl_down_sync(0xFFFFFFFFu, acc[k], o);

    if (slot == 0) {
        if (LAYER1) {
            uint4 o;
            *reinterpret_cast<__half2*>(&o.x) = __floats2half2_rn(acc[0], acc[1]);
            *reinterpret_cast<__half2*>(&o.y) = __floats2half2_rn(acc[2], acc[3]);
            *reinterpret_cast<__half2*>(&o.z) = __floats2half2_rn(acc[4], acc[5]);
            *reinterpret_cast<__half2*>(&o.w) = __floats2half2_rn(acc[6], acc[7]);
            reinterpret_cast<uint4*>(g_agg1)[(size_t)n * 8 + fl] = o;
        } else {
            float nd = g_norm_dst[n];
            float4 b0 = reinterpret_cast<const float4*>(bias)[fl * 2];
            float4 b1 = reinterpret_cast<const float4*>(bias)[fl * 2 + 1];
            float* op = out_arg + (size_t)n * 64 + fl * 8;
            *reinterpret_cast<float4*>(op) = make_float4(
                fmaf(acc[0], nd, b0.x), fmaf(acc[1], nd, b0.y),
                fmaf(acc[2], nd, b0.z), fmaf(acc[3], nd, b0.w));
            *reinterpret_cast<float4*>(op + 4) = make_float4(
                fmaf(acc[4], nd, b1.x), fmaf(acc[5], nd, b1.y),
                fmaf(acc[6], nd, b1.z), fmaf(acc[7], nd, b1.w));
        }
    }
}

// ---------------- FUSED GEMM (R13-proven): h2 = ((relu((agg1@W1)*nd + b1)) * ns) @ W2 ----------------
#define F_AS_STRIDE  76
#define F_WS1_OFF    (128 * F_AS_STRIDE)       // 9728
#define F_WS1_STRIDE 132
#define F_H1_STRIDE  132
#define F_WS2_OFF    18176
#define F_WS2_STRIDE 68
#define F_SB1_OFF    (F_WS2_OFF + 128 * F_WS2_STRIDE)   // 26880
#define F_SNS_OFF    (F_SB1_OFF + 128)                  // 27008
#define F_SMEM       ((F_SNS_OFF + 128) * 4)            // 108544 B

__global__ void __launch_bounds__(256) k_gemm_fused(const float* __restrict__ W1,
                                                    const float* __restrict__ b1,
                                                    const float* __restrict__ W2) {
    extern __shared__ float sm[];
    float* As  = sm;
    float* Ws1 = sm + F_WS1_OFF;
    float* H1s = sm;                 // overlays As+Ws1 after phase A
    float* Ws2 = sm + F_WS2_OFF;
    float* sb1 = sm + F_SB1_OFF;
    float* sns = sm + F_SNS_OFF;

    int tid = threadIdx.x;
    int row0 = blockIdx.x * 128;

    #pragma unroll
    for (int it = 0; it < 4; it++) {
        int idx = tid + it * 256;
        int r = idx >> 3, c8 = idx & 7;
        int row = row0 + r;
        float f[8] = {0.f, 0.f, 0.f, 0.f, 0.f, 0.f, 0.f, 0.f};
        if (row < NN) {
            uint4 raw = reinterpret_cast<const uint4*>(g_agg1)[(size_t)row * 8 + c8];
            h8_to_f8(raw, f);
        }
        float* p = &As[r * F_AS_STRIDE + c8 * 8];
        #pragma unroll
        for (int k = 0; k < 8; k++) p[k] = __uint_as_float(f2tf32(f[k]));
    }
    #pragma unroll
    for (int it = 0; it < 8; it++) {
        int idx4 = tid + it * 256;
        int k = idx4 >> 5, c4 = idx4 & 31;
        float4 v = *reinterpret_cast<const float4*>(&W1[(size_t)k * 128 + c4 * 4]);
        float* p = &Ws1[k * F_WS1_STRIDE + c4 * 4];
        p[0] = __uint_as_float(f2tf32(v.x)); p[1] = __uint_as_float(f2tf32(v.y));
        p[2] = __uint_as_float(f2tf32(v.z)); p[3] = __uint_as_float(f2tf32(v.w));
    }
    #pragma unroll
    for (int it = 0; it < 8; it++) {
        int idx4 = tid + it * 256;
        int k = idx4 >> 4, c4 = idx4 & 15;
        float4 v = *reinterpret_cast<const float4*>(&W2[(size_t)k * 64 + c4 * 4]);
        float* p = &Ws2[k * F_WS2_STRIDE + c4 * 4];
        p[0] = __uint_as_float(f2tf32(v.x)); p[1] = __uint_as_float(f2tf32(v.y));
        p[2] = __uint_as_float(f2tf32(v.z)); p[3] = __uint_as_float(f2tf32(v.w));
    }
    if (tid < 128) {
        sb1[tid] = b1[tid];
        int row = row0 + tid;
        sns[tid] = (row < NN) ? g_norm_src[row] : 0.f;
    }
    __syncthreads();

    int w = tid >> 5, lane = tid & 31;
    int wr = w >> 1, wc = w & 1;
    int g = lane >> 2, t4 = lane & 3;

    const uint32_t* Au = reinterpret_cast<const uint32_t*>(As);
    const uint32_t* W1u = reinterpret_cast<const uint32_t*>(Ws1);

    float c1[2][8][4];
    #pragma unroll
    for (int i = 0; i < 2; i++)
        #pragma unroll
        for (int j = 0; j < 8; j++)
            #pragma unroll
            for (int q = 0; q < 4; q++) c1[i][j][q] = 0.f;

    #pragma unroll
    for (int ks = 0; ks < 8; ks++) {
        int kb = ks * 8;
        uint32_t a[2][4];
        #pragma unroll
        for (int rf = 0; rf < 2; rf++) {
            int R = wr * 32 + rf * 16;
            a[rf][0] = Au[(R + g) * F_AS_STRIDE + kb + t4];
            a[rf][1] = Au[(R + 8 + g) * F_AS_STRIDE + kb + t4];
            a[rf][2] = Au[(R + g) * F_AS_STRIDE + kb + 4 + t4];
            a[rf][3] = Au[(R + 8 + g) * F_AS_STRIDE + kb + 4 + t4];
        }
        #pragma unroll
        for (int cf = 0; cf < 8; cf++) {
            int C = wc * 64 + cf * 8 + g;
            uint32_t b0 = W1u[(kb + t4) * F_WS1_STRIDE + C];
            uint32_t b1r = W1u[(kb + 4 + t4) * F_WS1_STRIDE + C];
            #pragma unroll
            for (int rf = 0; rf < 2; rf++)
                MMA_TF32(c1[rf][cf][0], c1[rf][cf][1], c1[rf][cf][2], c1[rf][cf][3],
                         a[rf][0], a[rf][1], a[rf][2], a[rf][3], b0, b1r);
        }
    }
    __syncthreads();

    #pragma unroll
    for (int rf = 0; rf < 2; rf++) {
        int lr1 = wr * 32 + rf * 16 + g;
        int lr2 = lr1 + 8;
        int r1 = row0 + lr1, r2 = row0 + lr2;
        float nd1 = (r1 < NN) ? g_norm_dst[r1] : 0.f;
        float nd2 = (r2 < NN) ? g_norm_dst[r2] : 0.f;
        float ns1 = sns[lr1], ns2 = sns[lr2];
        #pragma unroll
        for (int cf = 0; cf < 8; cf++) {
            int col = wc * 64 + cf * 8 + 2 * t4;
            float bx = sb1[col], by = sb1[col + 1];
            float v;
            v = fmaxf(fmaf(c1[rf][cf][0], nd1, bx), 0.f) * ns1;
            H1s[lr1 * F_H1_STRIDE + col]     = __uint_as_float(f2tf32(v));
            v = fmaxf(fmaf(c1[rf][cf][1], nd1, by), 0.f) * ns1;
            H1s[lr1 * F_H1_STRIDE + col + 1] = __uint_as_float(f2tf32(v));
            v = fmaxf(fmaf(c1[rf][cf][2], nd2, bx), 0.f) * ns2;
            H1s[lr2 * F_H1_STRIDE + col]     = __uint_as_float(f2tf32(v));
            v = fmaxf(fmaf(c1[rf][cf][3], nd2, by), 0.f) * ns2;
            H1s[lr2 * F_H1_STRIDE + col + 1] = __uint_as_float(f2tf32(v));
        }
    }
    __syncthreads();

    const uint32_t* Hu = reinterpret_cast<const uint32_t*>(H1s);
    const uint32_t* W2u = reinterpret_cast<const uint32_t*>(Ws2);

    float c2[2][4][4];
    #pragma unroll
    for (int i = 0; i < 2; i++)
        #pragma unroll
        for (int j = 0; j < 4; j++)
            #pragma unroll
            for (int q = 0; q < 4; q++) c2[i][j][q] = 0.f;

    #pragma unroll
    for (int ks = 0; ks < 16; ks++) {
        int kb = ks * 8;
        uint32_t a[2][4];
        #pragma unroll
        for (int rf = 0; rf < 2; rf++) {
            int R = wr * 32 + rf * 16;
            a[rf][0] = Hu[(R + g) * F_H1_STRIDE + kb + t4];
            a[rf][1] = Hu[(R + 8 + g) * F_H1_STRIDE + kb + t4];
            a[rf][2] = Hu[(R + g) * F_H1_STRIDE + kb + 4 + t4];
            a[rf][3] = Hu[(R + 8 + g) * F_H1_STRIDE + kb + 4 + t4];
        }
        #pragma unroll
        for (int cf = 0; cf < 4; cf++) {
            int C = wc * 32 + cf * 8 + g;
            uint32_t b0 = W2u[(kb + t4) * F_WS2_STRIDE + C];
            uint32_t b1r = W2u[(kb + 4 + t4) * F_WS2_STRIDE + C];
            #pragma unroll
            for (int rf = 0; rf < 2; rf++)
                MMA_TF32(c2[rf][cf][0], c2[rf][cf][1], c2[rf][cf][2], c2[rf][cf][3],
                         a[rf][0], a[rf][1], a[rf][2], a[rf][3], b0, b1r);
        }
    }

    #pragma unroll
    for (int rf = 0; rf < 2; rf++) {
        int r1 = row0 + wr * 32 + rf * 16 + g;
        int r2 = r1 + 8;
        #pragma unroll
        for (int cf = 0; cf < 4; cf++) {
            int col = wc * 32 + cf * 8 + 2 * t4;
            if (r1 < NN)
                *reinterpret_cast<__half2*>(&g_h2[(size_t)r1 * 64 + col]) =
                    __floats2half2_rn(c2[rf][cf][0], c2[rf][cf][1]);
            if (r2 < NN)
                *reinterpret_cast<__half2*>(&g_h2[(size_t)r2 * 64 + col]) =
                    __floats2half2_rn(c2[rf][cf][2], c2[rf][cf][3]);
        }
    }
}

// ---------------- launch ----------------
extern "C" void kernel_launch(void* const* d_in, const int* in_sizes, int n_in,
                              void* d_out, int out_size) {
    const float* x   = (const float*)d_in[0];
    const float* W1  = (const float*)d_in[1];
    const float* b1  = (const float*)d_in[2];
    const float* W2  = (const float*)d_in[3];
    const float* b2  = (const float*)d_in[4];
    const int*   src = (const int*)d_in[5];
    const int*   dst = (const int*)d_in[6];
    float* out = (float*)d_out;

    cudaFuncSetAttribute(k_gemm_fused, cudaFuncAttributeMaxDynamicSharedMemorySize, F_SMEM);

    k_zero<<<(NN + 255) / 256, 256>>>();
    k_degree<<<(EE + 255) / 256, 256>>>(src, dst);
    k_scan_blk<<<SCAN_BLK, 1024>>>();
    k_scan_add<<<SCAN_BLK, 1024>>>(x);   // also converts x*norm_src -> fp16
    k_scatter<<<(EE + 255) / 256, 256>>>(src, dst);

    int ntiles = (NN + 127) / 128;   // 391
    k_agg<true><<<NN / 8, 256>>>(nullptr, nullptr);
    k_gemm_fused<<<ntiles, 256, F_SMEM>>>(W1, b1, W2);
    k_agg<false><<<NN / 8, 256>>>(b2, out);
}

// round 16
// speedup vs baseline: 1.0223x; 1.0223x over previous
#include <cuda_runtime.h>
#include <cuda_fp16.h>
#include <cstdint>

#define NN 50000
#define EE 800000
#define SCAN_BLK ((NN + 1023) / 1024)   // 49

// ---------------- device scratch (no allocations allowed) ----------------
__device__ __align__(16) int    g_outdeg[NN];
__device__ __align__(16) int    g_indeg[NN];
__device__ __align__(16) int    g_cursor[NN];
__device__ __align__(16) int    g_rowptr[NN + 1];
__device__ __align__(16) int    g_esrc[EE];
__device__ __align__(16) int    g_bsum[SCAN_BLK];
__device__ __align__(16) float  g_norm_src[NN];
__device__ __align__(16) float  g_norm_dst[NN];
__device__ __align__(16) __half g_x16[(size_t)NN * 64];   // x * norm_src, fp16
__device__ __align__(16) __half g_agg1[(size_t)NN * 64];
__device__ __align__(16) __half g_h2[(size_t)NN * 64];

__device__ __forceinline__ uint32_t f2tf32(float v) {
    uint32_t u;
    asm("cvt.rna.tf32.f32 %0, %1;" : "=r"(u) : "f"(v));
    return u;
}

#define MMA_TF32(c0, c1, c2, c3, a0, a1, a2, a3, b0, b1) \
    asm volatile("mma.sync.aligned.m16n8k8.row.col.f32.tf32.tf32.f32 " \
        "{%0,%1,%2,%3}, {%4,%5,%6,%7}, {%8,%9}, {%0,%1,%2,%3};" \
        : "+f"(c0), "+f"(c1), "+f"(c2), "+f"(c3) \
        : "r"(a0), "r"(a1), "r"(a2), "r"(a3), "r"(b0), "r"(b1))

__device__ __forceinline__ void h8_to_f8(uint4 raw, float* f) {
    float2 p;
    p = __half22float2(*reinterpret_cast<__half2*>(&raw.x)); f[0] = p.x; f[1] = p.y;
    p = __half22float2(*reinterpret_cast<__half2*>(&raw.y)); f[2] = p.x; f[3] = p.y;
    p = __half22float2(*reinterpret_cast<__half2*>(&raw.z)); f[4] = p.x; f[5] = p.y;
    p = __half22float2(*reinterpret_cast<__half2*>(&raw.w)); f[6] = p.x; f[7] = p.y;
}

// ---------------- preprocessing ----------------
__global__ void k_zero() {
    int i = blockIdx.x * blockDim.x + threadIdx.x;
    if (i < NN) { g_outdeg[i] = 0; g_indeg[i] = 0; }
}

__global__ void k_degree(const int* __restrict__ src, const int* __restrict__ dst) {
    int e = blockIdx.x * blockDim.x + threadIdx.x;
    if (e < EE) {
        atomicAdd(&g_outdeg[src[e]], 1);
        atomicAdd(&g_indeg[dst[e]], 1);
    }
}

// per-block inclusive scan of indeg; norms fused (R13-proven)
__global__ void k_scan_blk() {
    __shared__ int sh[1024];
    int t = threadIdx.x;
    int i = blockIdx.x * 1024 + t;
    int deg = (i < NN) ? g_indeg[i] : 0;
    if (i < NN) {
        g_norm_dst[i] = rsqrtf((float)max(deg, 1));
        g_norm_src[i] = rsqrtf((float)max(g_outdeg[i], 1));
    }
    sh[t] = deg;
    __syncthreads();
    #pragma unroll
    for (int off = 1; off < 1024; off <<= 1) {
        int x = (t >= off) ? sh[t - off] : 0;
        __syncthreads();
        sh[t] += x;
        __syncthreads();
    }
    if (i < NN) g_rowptr[i + 1] = sh[t];
    if (t == 1023) g_bsum[blockIdx.x] = sh[1023];
}

// add block offsets + cursor init (R13-proven, no extra work)
__global__ void k_scan_add() {
    __shared__ int off;
    int t = threadIdx.x;
    int i = blockIdx.x * 1024 + t;
    if (t < 32) {
        int s = 0;
        for (int b = t; b < blockIdx.x; b += 32) s += g_bsum[b];
        #pragma unroll
        for (int o = 16; o > 0; o >>= 1) s += __shfl_down_sync(0xFFFFFFFFu, s, o);
        if (t == 0) off = s;
    }
    __syncthreads();
    if (i < NN) {
        int v = g_rowptr[i + 1] + off;
        g_rowptr[i + 1] = v;
        if (i + 1 < NN) g_cursor[i + 1] = v;
        if (i == 0) { g_rowptr[0] = 0; g_cursor[0] = 0; }
    }
}

// scatter (scalar, R9-proven) + FUSED x->fp16*norm_src conversion.
// Scatter is latency-bound (issue ~4%): the conversion's coalesced streaming
// work rides in the idle issue slots. Threads [0, NN*8) each convert one uint4.
__global__ void k_scatter(const int* __restrict__ src, const int* __restrict__ dst,
                          const float* __restrict__ x) {
    int e = blockIdx.x * blockDim.x + threadIdx.x;
    if (e < EE) {
        int pos = atomicAdd(&g_cursor[dst[e]], 1);
        g_esrc[pos] = src[e];
    }
    if (e < NN * 8) {
        int row = e >> 3, c8 = e & 7;
        float ns = g_norm_src[row];   // broadcast across 8 consecutive threads
        const float4* xp = reinterpret_cast<const float4*>(x) + (size_t)row * 16 + c8 * 2;
        float4 a = xp[0], b = xp[1];
        uint4 o;
        *reinterpret_cast<__half2*>(&o.x) = __floats2half2_rn(a.x * ns, a.y * ns);
        *reinterpret_cast<__half2*>(&o.y) = __floats2half2_rn(a.z * ns, a.w * ns);
        *reinterpret_cast<__half2*>(&o.z) = __floats2half2_rn(b.x * ns, b.y * ns);
        *reinterpret_cast<__half2*>(&o.w) = __floats2half2_rn(b.z * ns, b.w * ns);
        reinterpret_cast<uint4*>(g_x16)[e] = o;
    }
}

// ---------------- aggregation: plain sum (norm_src pre-folded into x16) ----------------
template <bool LAYER1>
__global__ void __launch_bounds__(256) k_agg(const float* __restrict__ bias,
                                             float* __restrict__ out_arg) {
    const uint4* __restrict__ feat = LAYER1
        ? reinterpret_cast<const uint4*>(g_x16)
        : reinterpret_cast<const uint4*>(g_h2);
    int n = blockIdx.x * 8 + (threadIdx.x >> 5);   // grid*8 == NN
    int lane = threadIdx.x & 31;
    int slot = lane >> 3;
    int fl   = lane & 7;

    int s = g_rowptr[n], e = g_rowptr[n + 1];
    float acc[8] = {0.f, 0.f, 0.f, 0.f, 0.f, 0.f, 0.f, 0.f};
    #pragma unroll 2
    for (int j = s + slot; j < e; j += 4) {
        int u = g_esrc[j];
        uint4 raw = feat[(size_t)u * 8 + fl];
        float f[8];
        h8_to_f8(raw, f);
        #pragma unroll
        for (int k = 0; k < 8; k++) acc[k] += f[k];
    }
    #pragma unroll
    for (int o = 16; o >= 8; o >>= 1)
        #pragma unroll
        for (int k = 0; k < 8; k++)
            acc[k] += __shfl_down_sync(0xFFFFFFFFu, acc[k], o);

    if (slot == 0) {
        if (LAYER1) {
            uint4 o;
            *reinterpret_cast<__half2*>(&o.x) = __floats2half2_rn(acc[0], acc[1]);
            *reinterpret_cast<__half2*>(&o.y) = __floats2half2_rn(acc[2], acc[3]);
            *reinterpret_cast<__half2*>(&o.z) = __floats2half2_rn(acc[4], acc[5]);
            *reinterpret_cast<__half2*>(&o.w) = __floats2half2_rn(acc[6], acc[7]);
            reinterpret_cast<uint4*>(g_agg1)[(size_t)n * 8 + fl] = o;
        } else {
            float nd = g_norm_dst[n];
            float4 b0 = reinterpret_cast<const float4*>(bias)[fl * 2];
            float4 b1 = reinterpret_cast<const float4*>(bias)[fl * 2 + 1];
            float* op = out_arg + (size_t)n * 64 + fl * 8;
            *reinterpret_cast<float4*>(op) = make_float4(
                fmaf(acc[0], nd, b0.x), fmaf(acc[1], nd, b0.y),
                fmaf(acc[2], nd, b0.z), fmaf(acc[3], nd, b0.w));
            *reinterpret_cast<float4*>(op + 4) = make_float4(
                fmaf(acc[4], nd, b1.x), fmaf(acc[5], nd, b1.y),
                fmaf(acc[6], nd, b1.z), fmaf(acc[7], nd, b1.w));
        }
    }
}

// ---------------- FUSED GEMM (R13-proven): h2 = ((relu((agg1@W1)*nd + b1)) * ns) @ W2 ----------------
#define F_AS_STRIDE  76
#define F_WS1_OFF    (128 * F_AS_STRIDE)       // 9728
#define F_WS1_STRIDE 132
#define F_H1_STRIDE  132
#define F_WS2_OFF    18176
#define F_WS2_STRIDE 68
#define F_SB1_OFF    (F_WS2_OFF + 128 * F_WS2_STRIDE)   // 26880
#define F_SNS_OFF    (F_SB1_OFF + 128)                  // 27008
#define F_SMEM       ((F_SNS_OFF + 128) * 4)            // 108544 B

__global__ void __launch_bounds__(256) k_gemm_fused(const float* __restrict__ W1,
                                                    const float* __restrict__ b1,
                                                    const float* __restrict__ W2) {
    extern __shared__ float sm[];
    float* As  = sm;
    float* Ws1 = sm + F_WS1_OFF;
    float* H1s = sm;                 // overlays As+Ws1 after phase A
    float* Ws2 = sm + F_WS2_OFF;
    float* sb1 = sm + F_SB1_OFF;
    float* sns = sm + F_SNS_OFF;

    int tid = threadIdx.x;
    int row0 = blockIdx.x * 128;

    #pragma unroll
    for (int it = 0; it < 4; it++) {
        int idx = tid + it * 256;
        int r = idx >> 3, c8 = idx & 7;
        int row = row0 + r;
        float f[8] = {0.f, 0.f, 0.f, 0.f, 0.f, 0.f, 0.f, 0.f};
        if (row < NN) {
            uint4 raw = reinterpret_cast<const uint4*>(g_agg1)[(size_t)row * 8 + c8];
            h8_to_f8(raw, f);
        }
        float* p = &As[r * F_AS_STRIDE + c8 * 8];
        #pragma unroll
        for (int k = 0; k < 8; k++) p[k] = __uint_as_float(f2tf32(f[k]));
    }
    #pragma unroll
    for (int it = 0; it < 8; it++) {
        int idx4 = tid + it * 256;
        int k = idx4 >> 5, c4 = idx4 & 31;
        float4 v = *reinterpret_cast<const float4*>(&W1[(size_t)k * 128 + c4 * 4]);
        float* p = &Ws1[k * F_WS1_STRIDE + c4 * 4];
        p[0] = __uint_as_float(f2tf32(v.x)); p[1] = __uint_as_float(f2tf32(v.y));
        p[2] = __uint_as_float(f2tf32(v.z)); p[3] = __uint_as_float(f2tf32(v.w));
    }
    #pragma unroll
    for (int it = 0; it < 8; it++) {
        int idx4 = tid + it * 256;
        int k = idx4 >> 4, c4 = idx4 & 15;
        float4 v = *reinterpret_cast<const float4*>(&W2[(size_t)k * 64 + c4 * 4]);
        float* p = &Ws2[k * F_WS2_STRIDE + c4 * 4];
        p[0] = __uint_as_float(f2tf32(v.x)); p[1] = __uint_as_float(f2tf32(v.y));
        p[2] = __uint_as_float(f2tf32(v.z)); p[3] = __uint_as_float(f2tf32(v.w));
    }
    if (tid < 128) {
        sb1[tid] = b1[tid];
        int row = row0 + tid;
        sns[tid] = (row < NN) ? g_norm_src[row] : 0.f;
    }
    __syncthreads();

    int w = tid >> 5, lane = tid & 31;
    int wr = w >> 1, wc = w & 1;
    int g = lane >> 2, t4 = lane & 3;

    const uint32_t* Au = reinterpret_cast<const uint32_t*>(As);
    const uint32_t* W1u = reinterpret_cast<const uint32_t*>(Ws1);

    float c1[2][8][4];
    #pragma unroll
    for (int i = 0; i < 2; i++)
        #pragma unroll
        for (int j = 0; j < 8; j++)
            #pragma unroll
            for (int q = 0; q < 4; q++) c1[i][j][q] = 0.f;

    #pragma unroll
    for (int ks = 0; ks < 8; ks++) {
        int kb = ks * 8;
        uint32_t a[2][4];
        #pragma unroll
        for (int rf = 0; rf < 2; rf++) {
            int R = wr * 32 + rf * 16;
            a[rf][0] = Au[(R + g) * F_AS_STRIDE + kb + t4];
            a[rf][1] = Au[(R + 8 + g) * F_AS_STRIDE + kb + t4];
            a[rf][2] = Au[(R + g) * F_AS_STRIDE + kb + 4 + t4];
            a[rf][3] = Au[(R + 8 + g) * F_AS_STRIDE + kb + 4 + t4];
        }
        #pragma unroll
        for (int cf = 0; cf < 8; cf++) {
            int C = wc * 64 + cf * 8 + g;
            uint32_t b0 = W1u[(kb + t4) * F_WS1_STRIDE + C];
            uint32_t b1r = W1u[(kb + 4 + t4) * F_WS1_STRIDE + C];
            #pragma unroll
            for (int rf = 0; rf < 2; rf++)
                MMA_TF32(c1[rf][cf][0], c1[rf][cf][1], c1[rf][cf][2], c1[rf][cf][3],
                         a[rf][0], a[rf][1], a[rf][2], a[rf][3], b0, b1r);
        }
    }
    __syncthreads();

    #pragma unroll
    for (int rf = 0; rf < 2; rf++) {
        int lr1 = wr * 32 + rf * 16 + g;
        int lr2 = lr1 + 8;
        int r1 = row0 + lr1, r2 = row0 + lr2;
        float nd1 = (r1 < NN) ? g_norm_dst[r1] : 0.f;
        float nd2 = (r2 < NN) ? g_norm_dst[r2] : 0.f;
        float ns1 = sns[lr1], ns2 = sns[lr2];
        #pragma unroll
        for (int cf = 0; cf < 8; cf++) {
            int col = wc * 64 + cf * 8 + 2 * t4;
            float bx = sb1[col], by = sb1[col + 1];
            float v;
            v = fmaxf(fmaf(c1[rf][cf][0], nd1, bx), 0.f) * ns1;
            H1s[lr1 * F_H1_STRIDE + col]     = __uint_as_float(f2tf32(v));
            v = fmaxf(fmaf(c1[rf][cf][1], nd1, by), 0.f) * ns1;
            H1s[lr1 * F_H1_STRIDE + col + 1] = __uint_as_float(f2tf32(v));
            v = fmaxf(fmaf(c1[rf][cf][2], nd2, bx), 0.f) * ns2;
            H1s[lr2 * F_H1_STRIDE + col]     = __uint_as_float(f2tf32(v));
            v = fmaxf(fmaf(c1[rf][cf][3], nd2, by), 0.f) * ns2;
            H1s[lr2 * F_H1_STRIDE + col + 1] = __uint_as_float(f2tf32(v));
        }
    }
    __syncthreads();

    const uint32_t* Hu = reinterpret_cast<const uint32_t*>(H1s);
    const uint32_t* W2u = reinterpret_cast<const uint32_t*>(Ws2);

    float c2[2][4][4];
    #pragma unroll
    for (int i = 0; i < 2; i++)
        #pragma unroll
        for (int j = 0; j < 4; j++)
            #pragma unroll
            for (int q = 0; q < 4; q++) c2[i][j][q] = 0.f;

    #pragma unroll
    for (int ks = 0; ks < 16; ks++) {
        int kb = ks * 8;
        uint32_t a[2][4];
        #pragma unroll
        for (int rf = 0; rf < 2; rf++) {
            int R = wr * 32 + rf * 16;
            a[rf][0] = Hu[(R + g) * F_H1_STRIDE + kb + t4];
            a[rf][1] = Hu[(R + 8 + g) * F_H1_STRIDE + kb + t4];
            a[rf][2] = Hu[(R + g) * F_H1_STRIDE + kb + 4 + t4];
            a[rf][3] = Hu[(R + 8 + g) * F_H1_STRIDE + kb + 4 + t4];
        }
        #pragma unroll
        for (int cf = 0; cf < 4; cf++) {
            int C = wc * 32 + cf * 8 + g;
            uint32_t b0 = W2u[(kb + t4) * F_WS2_STRIDE + C];
            uint32_t b1r = W2u[(kb + 4 + t4) * F_WS2_STRIDE + C];
            #pragma unroll
            for (int rf = 0; rf < 2; rf++)
                MMA_TF32(c2[rf][cf][0], c2[rf][cf][1], c2[rf][cf][2], c2[rf][cf][3],
                         a[rf][0], a[rf][1], a[rf][2], a[rf][3], b0, b1r);
        }
    }

    #pragma unroll
    for (int rf = 0; rf < 2; rf++) {
        int r1 = row0 + wr * 32 + rf * 16 + g;
        int r2 = r1 + 8;
        #pragma unroll
        for (int cf = 0; cf < 4; cf++) {
            int col = wc * 32 + cf * 8 + 2 * t4;
            if (r1 < NN)
                *reinterpret_cast<__half2*>(&g_h2[(size_t)r1 * 64 + col]) =
                    __floats2half2_rn(c2[rf][cf][0], c2[rf][cf][1]);
            if (r2 < NN)
                *reinterpret_cast<__half2*>(&g_h2[(size_t)r2 * 64 + col]) =
                    __floats2half2_rn(c2[rf][cf][2], c2[rf][cf][3]);
        }
    }
}

// ---------------- launch ----------------
extern "C" void kernel_launch(void* const* d_in, const int* in_sizes, int n_in,
                              void* d_out, int out_size) {
    const float* x   = (const float*)d_in[0];
    const float* W1  = (const float*)d_in[1];
    const float* b1  = (const float*)d_in[2];
    const float* W2  = (const float*)d_in[3];
    const float* b2  = (const float*)d_in[4];
    const int*   src = (const int*)d_in[5];
    const int*   dst = (const int*)d_in[6];
    float* out = (float*)d_out;

    cudaFuncSetAttribute(k_gemm_fused, cudaFuncAttributeMaxDynamicSharedMemorySize, F_SMEM);

    k_zero<<<(NN + 255) / 256, 256>>>();
    k_degree<<<(EE + 255) / 256, 256>>>(src, dst);
    k_scan_blk<<<SCAN_BLK, 1024>>>();
    k_scan_add<<<SCAN_BLK, 1024>>>();
    k_scatter<<<(EE + 255) / 256, 256>>>(src, dst, x);   // + fused x*ns -> fp16

    int ntiles = (NN + 127) / 128;   // 391
    k_agg<true><<<NN / 8, 256>>>(nullptr, nullptr);
    k_gemm_fused<<<ntiles, 256, F_SMEM>>>(W1, b1, W2);
    k_agg<false><<<NN / 8, 256>>>(b2, out);
}

// round 17
// speedup vs baseline: 1.0492x; 1.0263x over previous
#include <cuda_runtime.h>
#include <cuda_fp16.h>
#include <cstdint>

#define NN 50000
#define EE 800000
#define SCAN_BLK ((NN + 1023) / 1024)   // 49

// ---------------- device scratch (no allocations allowed) ----------------
// NOTE: zero-initialized at module load; k_agg<false> tail re-zeroes
// g_outdeg/g_indeg each call so every graph replay starts identically.
__device__ __align__(16) int    g_outdeg[NN];
__device__ __align__(16) int    g_indeg[NN];
__device__ __align__(16) int    g_cursor[NN];
__device__ __align__(16) int    g_rowptr[NN + 1];
__device__ __align__(16) int    g_esrc[EE];
__device__ __align__(16) int    g_bsum[SCAN_BLK];
__device__ __align__(16) float  g_norm_src[NN];
__device__ __align__(16) float  g_norm_dst[NN];
__device__ __align__(16) __half g_x16[(size_t)NN * 64];   // x * norm_src, fp16
__device__ __align__(16) __half g_agg1[(size_t)NN * 64];
__device__ __align__(16) __half g_h2[(size_t)NN * 64];

__device__ __forceinline__ uint32_t f2tf32(float v) {
    uint32_t u;
    asm("cvt.rna.tf32.f32 %0, %1;" : "=r"(u) : "f"(v));
    return u;
}

#define MMA_TF32(c0, c1, c2, c3, a0, a1, a2, a3, b0, b1) \
    asm volatile("mma.sync.aligned.m16n8k8.row.col.f32.tf32.tf32.f32 " \
        "{%0,%1,%2,%3}, {%4,%5,%6,%7}, {%8,%9}, {%0,%1,%2,%3};" \
        : "+f"(c0), "+f"(c1), "+f"(c2), "+f"(c3) \
        : "r"(a0), "r"(a1), "r"(a2), "r"(a3), "r"(b0), "r"(b1))

__device__ __forceinline__ void h8_to_f8(uint4 raw, float* f) {
    float2 p;
    p = __half22float2(*reinterpret_cast<__half2*>(&raw.x)); f[0] = p.x; f[1] = p.y;
    p = __half22float2(*reinterpret_cast<__half2*>(&raw.y)); f[2] = p.x; f[3] = p.y;
    p = __half22float2(*reinterpret_cast<__half2*>(&raw.z)); f[4] = p.x; f[5] = p.y;
    p = __half22float2(*reinterpret_cast<__half2*>(&raw.w)); f[6] = p.x; f[7] = p.y;
}

// ---------------- preprocessing ----------------
__global__ void k_degree(const int* __restrict__ src, const int* __restrict__ dst) {
    int e = blockIdx.x * blockDim.x + threadIdx.x;
    if (e < EE) {
        atomicAdd(&g_outdeg[src[e]], 1);
        atomicAdd(&g_indeg[dst[e]], 1);
    }
}

// per-block inclusive scan of indeg (warp-shuffle: 2 barriers); norms fused
__global__ void k_scan_blk() {
    __shared__ int wsum[32];
    int t = threadIdx.x;
    int i = blockIdx.x * 1024 + t;
    int lane = t & 31, wid = t >> 5;

    int deg = (i < NN) ? g_indeg[i] : 0;
    if (i < NN) {
        g_norm_dst[i] = rsqrtf((float)max(deg, 1));
        g_norm_src[i] = rsqrtf((float)max(g_outdeg[i], 1));
    }
    // per-warp inclusive scan
    int v = deg;
    #pragma unroll
    for (int o = 1; o < 32; o <<= 1) {
        int x = __shfl_up_sync(0xFFFFFFFFu, v, o);
        if (lane >= o) v += x;
    }
    if (lane == 31) wsum[wid] = v;
    __syncthreads();
    // warp 0 scans the 32 warp sums
    if (wid == 0) {
        int s = wsum[lane];
        #pragma unroll
        for (int o = 1; o < 32; o <<= 1) {
            int x = __shfl_up_sync(0xFFFFFFFFu, s, o);
            if (lane >= o) s += x;
        }
        wsum[lane] = s;
    }
    __syncthreads();
    if (wid > 0) v += wsum[wid - 1];
    if (i < NN) g_rowptr[i + 1] = v;
    if (t == 1023) g_bsum[blockIdx.x] = v;
}

// add block offsets + cursor init (R13-proven)
__global__ void k_scan_add() {
    __shared__ int off;
    int t = threadIdx.x;
    int i = blockIdx.x * 1024 + t;
    if (t < 32) {
        int s = 0;
        for (int b = t; b < blockIdx.x; b += 32) s += g_bsum[b];
        #pragma unroll
        for (int o = 16; o > 0; o >>= 1) s += __shfl_down_sync(0xFFFFFFFFu, s, o);
        if (t == 0) off = s;
    }
    __syncthreads();
    if (i < NN) {
        int v = g_rowptr[i + 1] + off;
        g_rowptr[i + 1] = v;
        if (i + 1 < NN) g_cursor[i + 1] = v;
        if (i == 0) { g_rowptr[0] = 0; g_cursor[0] = 0; }
    }
}

// scatter (scalar) + fused x->fp16*norm_src conversion (R16-proven neutral-or-better)
__global__ void k_scatter(const int* __restrict__ src, const int* __restrict__ dst,
                          const float* __restrict__ x) {
    int e = blockIdx.x * blockDim.x + threadIdx.x;
    if (e < EE) {
        int pos = atomicAdd(&g_cursor[dst[e]], 1);
        g_esrc[pos] = src[e];
    }
    if (e < NN * 8) {
        int row = e >> 3, c8 = e & 7;
        float ns = g_norm_src[row];
        const float4* xp = reinterpret_cast<const float4*>(x) + (size_t)row * 16 + c8 * 2;
        float4 a = xp[0], b = xp[1];
        uint4 o;
        *reinterpret_cast<__half2*>(&o.x) = __floats2half2_rn(a.x * ns, a.y * ns);
        *reinterpret_cast<__half2*>(&o.y) = __floats2half2_rn(a.z * ns, a.w * ns);
        *reinterpret_cast<__half2*>(&o.z) = __floats2half2_rn(b.x * ns, b.y * ns);
        *reinterpret_cast<__half2*>(&o.w) = __floats2half2_rn(b.z * ns, b.w * ns);
        reinterpret_cast<uint4*>(g_x16)[e] = o;
    }
}

// ---------------- aggregation: plain sum; layer-2 tail re-zeroes counters ----------------
template <bool LAYER1>
__global__ void __launch_bounds__(256) k_agg(const float* __restrict__ bias,
                                             float* __restrict__ out_arg) {
    const uint4* __restrict__ feat = LAYER1
        ? reinterpret_cast<const uint4*>(g_x16)
        : reinterpret_cast<const uint4*>(g_h2);
    int n = blockIdx.x * 8 + (threadIdx.x >> 5);   // grid*8 == NN
    int lane = threadIdx.x & 31;
    int slot = lane >> 3;
    int fl   = lane & 7;

    int s = g_rowptr[n], e = g_rowptr[n + 1];
    float acc[8] = {0.f, 0.f, 0.f, 0.f, 0.f, 0.f, 0.f, 0.f};
    #pragma unroll 2
    for (int j = s + slot; j < e; j += 4) {
        int u = g_esrc[j];
        uint4 raw = feat[(size_t)u * 8 + fl];
        float f[8];
        h8_to_f8(raw, f);
        #pragma unroll
        for (int k = 0; k < 8; k++) acc[k] += f[k];
    }
    #pragma unroll
    for (int o = 16; o >= 8; o >>= 1)
        #pragma unroll
        for (int k = 0; k < 8; k++)
            acc[k] += __shfl_down_sync(0xFFFFFFFFu, acc[k], o);

    if (slot == 0) {
        if (LAYER1) {
            uint4 o;
            *reinterpret_cast<__half2*>(&o.x) = __floats2half2_rn(acc[0], acc[1]);
            *reinterpret_cast<__half2*>(&o.y) = __floats2half2_rn(acc[2], acc[3]);
            *reinterpret_cast<__half2*>(&o.z) = __floats2half2_rn(acc[4], acc[5]);
            *reinterpret_cast<__half2*>(&o.w) = __floats2half2_rn(acc[6], acc[7]);
            reinterpret_cast<uint4*>(g_agg1)[(size_t)n * 8 + fl] = o;
        } else {
            float nd = g_norm_dst[n];
            float4 b0 = reinterpret_cast<const float4*>(bias)[fl * 2];
            float4 b1 = reinterpret_cast<const float4*>(bias)[fl * 2 + 1];
            float* op = out_arg + (size_t)n * 64 + fl * 8;
            *reinterpret_cast<float4*>(op) = make_float4(
                fmaf(acc[0], nd, b0.x), fmaf(acc[1], nd, b0.y),
                fmaf(acc[2], nd, b0.z), fmaf(acc[3], nd, b0.w));
            *reinterpret_cast<float4*>(op + 4) = make_float4(
                fmaf(acc[4], nd, b1.x), fmaf(acc[5], nd, b1.y),
                fmaf(acc[6], nd, b1.z), fmaf(acc[7], nd, b1.w));
        }
    }
    // tail: re-zero degree counters for the next graph replay (dead by now;
    // module-load zero-init covers the very first call)
    if (!LAYER1) {
        int gid = blockIdx.x * 256 + threadIdx.x;   // 1.6M threads >= NN
        if (gid < NN) { g_outdeg[gid] = 0; g_indeg[gid] = 0; }
    }
}

// ---------------- FUSED GEMM (R13-proven): h2 = ((relu((agg1@W1)*nd + b1)) * ns) @ W2 ----------------
#define F_AS_STRIDE  76
#define F_WS1_OFF    (128 * F_AS_STRIDE)       // 9728
#define F_WS1_STRIDE 132
#define F_H1_STRIDE  132
#define F_WS2_OFF    18176
#define F_WS2_STRIDE 68
#define F_SB1_OFF    (F_WS2_OFF + 128 * F_WS2_STRIDE)   // 26880
#define F_SNS_OFF    (F_SB1_OFF + 128)                  // 27008
#define F_SMEM       ((F_SNS_OFF + 128) * 4)            // 108544 B

__global__ void __launch_bounds__(256) k_gemm_fused(const float* __restrict__ W1,
                                                    const float* __restrict__ b1,
                                                    const float* __restrict__ W2) {
    extern __shared__ float sm[];
    float* As  = sm;
    float* Ws1 = sm + F_WS1_OFF;
    float* H1s = sm;                 // overlays As+Ws1 after phase A
    float* Ws2 = sm + F_WS2_OFF;
    float* sb1 = sm + F_SB1_OFF;
    float* sns = sm + F_SNS_OFF;

    int tid = threadIdx.x;
    int row0 = blockIdx.x * 128;

    #pragma unroll
    for (int it = 0; it < 4; it++) {
        int idx = tid + it * 256;
        int r = idx >> 3, c8 = idx & 7;
        int row = row0 + r;
        float f[8] = {0.f, 0.f, 0.f, 0.f, 0.f, 0.f, 0.f, 0.f};
        if (row < NN) {
            uint4 raw = reinterpret_cast<const uint4*>(g_agg1)[(size_t)row * 8 + c8];
            h8_to_f8(raw, f);
        }
        float* p = &As[r * F_AS_STRIDE + c8 * 8];
        #pragma unroll
        for (int k = 0; k < 8; k++) p[k] = __uint_as_float(f2tf32(f[k]));
    }
    #pragma unroll
    for (int it = 0; it < 8; it++) {
        int idx4 = tid + it * 256;
        int k = idx4 >> 5, c4 = idx4 & 31;
        float4 v = *reinterpret_cast<const float4*>(&W1[(size_t)k * 128 + c4 * 4]);
        float* p = &Ws1[k * F_WS1_STRIDE + c4 * 4];
        p[0] = __uint_as_float(f2tf32(v.x)); p[1] = __uint_as_float(f2tf32(v.y));
        p[2] = __uint_as_float(f2tf32(v.z)); p[3] = __uint_as_float(f2tf32(v.w));
    }
    #pragma unroll
    for (int it = 0; it < 8; it++) {
        int idx4 = tid + it * 256;
        int k = idx4 >> 4, c4 = idx4 & 15;
        float4 v = *reinterpret_cast<const float4*>(&W2[(size_t)k * 64 + c4 * 4]);
        float* p = &Ws2[k * F_WS2_STRIDE + c4 * 4];
        p[0] = __uint_as_float(f2tf32(v.x)); p[1] = __uint_as_float(f2tf32(v.y));
        p[2] = __uint_as_float(f2tf32(v.z)); p[3] = __uint_as_float(f2tf32(v.w));
    }
    if (tid < 128) {
        sb1[tid] = b1[tid];
        int row = row0 + tid;
        sns[tid] = (row < NN) ? g_norm_src[row] : 0.f;
    }
    __syncthreads();

    int w = tid >> 5, lane = tid & 31;
    int wr = w >> 1, wc = w & 1;
    int g = lane >> 2, t4 = lane & 3;

    const uint32_t* Au = reinterpret_cast<const uint32_t*>(As);
    const uint32_t* W1u = reinterpret_cast<const uint32_t*>(Ws1);

    float c1[2][8][4];
    #pragma unroll
    for (int i = 0; i < 2; i++)
        #pragma unroll
        for (int j = 0; j < 8; j++)
            #pragma unroll
            for (int q = 0; q < 4; q++) c1[i][j][q] = 0.f;

    #pragma unroll
    for (int ks = 0; ks < 8; ks++) {
        int kb = ks * 8;
        uint32_t a[2][4];
        #pragma unroll
        for (int rf = 0; rf < 2; rf++) {
            int R = wr * 32 + rf * 16;
            a[rf][0] = Au[(R + g) * F_AS_STRIDE + kb + t4];
            a[rf][1] = Au[(R + 8 + g) * F_AS_STRIDE + kb + t4];
            a[rf][2] = Au[(R + g) * F_AS_STRIDE + kb + 4 + t4];
            a[rf][3] = Au[(R + 8 + g) * F_AS_STRIDE + kb + 4 + t4];
        }
        #pragma unroll
        for (int cf = 0; cf < 8; cf++) {
            int C = wc * 64 + cf * 8 + g;
            uint32_t b0 = W1u[(kb + t4) * F_WS1_STRIDE + C];
            uint32_t b1r = W1u[(kb + 4 + t4) * F_WS1_STRIDE + C];
            #pragma unroll
            for (int rf = 0; rf < 2; rf++)
                MMA_TF32(c1[rf][cf][0], c1[rf][cf][1], c1[rf][cf][2], c1[rf][cf][3],
                         a[rf][0], a[rf][1], a[rf][2], a[rf][3], b0, b1r);
        }
    }
    __syncthreads();

    #pragma unroll
    for (int rf = 0; rf < 2; rf++) {
        int lr1 = wr * 32 + rf * 16 + g;
        int lr2 = lr1 + 8;
        int r1 = row0 + lr1, r2 = row0 + lr2;
        float nd1 = (r1 < NN) ? g_norm_dst[r1] : 0.f;
        float nd2 = (r2 < NN) ? g_norm_dst[r2] : 0.f;
        float ns1 = sns[lr1], ns2 = sns[lr2];
        #pragma unroll
        for (int cf = 0; cf < 8; cf++) {
            int col = wc * 64 + cf * 8 + 2 * t4;
            float bx = sb1[col], by = sb1[col + 1];
            float v;
            v = fmaxf(fmaf(c1[rf][cf][0], nd1, bx), 0.f) * ns1;
            H1s[lr1 * F_H1_STRIDE + col]     = __uint_as_float(f2tf32(v));
            v = fmaxf(fmaf(c1[rf][cf][1], nd1, by), 0.f) * ns1;
            H1s[lr1 * F_H1_STRIDE + col + 1] = __uint_as_float(f2tf32(v));
            v = fmaxf(fmaf(c1[rf][cf][2], nd2, bx), 0.f) * ns2;
            H1s[lr2 * F_H1_STRIDE + col]     = __uint_as_float(f2tf32(v));
            v = fmaxf(fmaf(c1[rf][cf][3], nd2, by), 0.f) * ns2;
            H1s[lr2 * F_H1_STRIDE + col + 1] = __uint_as_float(f2tf32(v));
        }
    }
    __syncthreads();

    const uint32_t* Hu = reinterpret_cast<const uint32_t*>(H1s);
    const uint32_t* W2u = reinterpret_cast<const uint32_t*>(Ws2);

    float c2[2][4][4];
    #pragma unroll
    for (int i = 0; i < 2; i++)
        #pragma unroll
        for (int j = 0; j < 4; j++)
            #pragma unroll
            for (int q = 0; q < 4; q++) c2[i][j][q] = 0.f;

    #pragma unroll
    for (int ks = 0; ks < 16; ks++) {
        int kb = ks * 8;
        uint32_t a[2][4];
        #pragma unroll
        for (int rf = 0; rf < 2; rf++) {
            int R = wr * 32 + rf * 16;
            a[rf][0] = Hu[(R + g) * F_H1_STRIDE + kb + t4];
            a[rf][1] = Hu[(R + 8 + g) * F_H1_STRIDE + kb + t4];
            a[rf][2] = Hu[(R + g) * F_H1_STRIDE + kb + 4 + t4];
            a[rf][3] = Hu[(R + 8 + g) * F_H1_STRIDE + kb + 4 + t4];
        }
        #pragma unroll
        for (int cf = 0; cf < 4; cf++) {
            int C = wc * 32 + cf * 8 + g;
            uint32_t b0 = W2u[(kb + t4) * F_WS2_STRIDE + C];
            uint32_t b1r = W2u[(kb + 4 + t4) * F_WS2_STRIDE + C];
            #pragma unroll
            for (int rf = 0; rf < 2; rf++)
                MMA_TF32(c2[rf][cf][0], c2[rf][cf][1], c2[rf][cf][2], c2[rf][cf][3],
                         a[rf][0], a[rf][1], a[rf][2], a[rf][3], b0, b1r);
        }
    }

    #pragma unroll
    for (int rf = 0; rf < 2; rf++) {
        int r1 = row0 + wr * 32 + rf * 16 + g;
        int r2 = r1 + 8;
        #pragma unroll
        for (int cf = 0; cf < 4; cf++) {
            int col = wc * 32 + cf * 8 + 2 * t4;
            if (r1 < NN)
                *reinterpret_cast<__half2*>(&g_h2[(size_t)r1 * 64 + col]) =
                    __floats2half2_rn(c2[rf][cf][0], c2[rf][cf][1]);
            if (r2 < NN)
                *reinterpret_cast<__half2*>(&g_h2[(size_t)r2 * 64 + col]) =
                    __floats2half2_rn(c2[rf][cf][2], c2[rf][cf][3]);
        }
    }
}

// ---------------- launch ----------------
extern "C" void kernel_launch(void* const* d_in, const int* in_sizes, int n_in,
                              void* d_out, int out_size) {
    const float* x   = (const float*)d_in[0];
    const float* W1  = (const float*)d_in[1];
    const float* b1  = (const float*)d_in[2];
    const float* W2  = (const float*)d_in[3];
    const float* b2  = (const float*)d_in[4];
    const int*   src = (const int*)d_in[5];
    const int*   dst = (const int*)d_in[6];
    float* out = (float*)d_out;

    cudaFuncSetAttribute(k_gemm_fused, cudaFuncAttributeMaxDynamicSharedMemorySize, F_SMEM);

    // counters zeroed by module-load init (first call) / previous call's k_agg<false> tail
    k_degree<<<(EE + 255) / 256, 256>>>(src, dst);
    k_scan_blk<<<SCAN_BLK, 1024>>>();
    k_scan_add<<<SCAN_BLK, 1024>>>();
    k_scatter<<<(EE + 255) / 256, 256>>>(src, dst, x);   // + fused x*ns -> fp16

    int ntiles = (NN + 127) / 128;   // 391
    k_agg<true><<<NN / 8, 256>>>(nullptr, nullptr);
    k_gemm_fused<<<ntiles, 256, F_SMEM>>>(W1, b1, W2);
    k_agg<false><<<NN / 8, 256>>>(b2, out);               // tail re-zeroes counters
}